// round 1
// baseline (speedup 1.0000x reference)
#include <cuda_runtime.h>
#include <cuda_bf16.h>
#include <math.h>

#define N_PTS   262144
#define N_FREQS 10
#define ENC_DIM 63
#define HID     128
#define NLAYERS 5
#define KDIM    191   // HID + ENC_DIM
#define OUTD    48
#define ORDER   16
#define BLK     64    // points per CTA
#define THREADS 128

__device__ __forceinline__ float3 norm3(float3 v, float eps) {
    float n = sqrtf(v.x*v.x + v.y*v.y + v.z*v.z);
    float inv = 1.0f / fmaxf(n, eps);
    return make_float3(v.x*inv, v.y*inv, v.z*inv);
}
__device__ __forceinline__ float3 cross3(float3 a, float3 b) {
    return make_float3(a.y*b.z - a.z*b.y, a.z*b.x - a.x*b.z, a.x*b.y - a.y*b.x);
}

extern "C" __global__ void __launch_bounds__(THREADS)
fourier_mlp_kernel(const float* __restrict__ x, const float* __restrict__ view,
                   const float* __restrict__ normal, const float* __restrict__ light,
                   const float* __restrict__ W0, const float* __restrict__ b0,
                   const float* __restrict__ Wh, const float* __restrict__ bh,
                   const float* __restrict__ Wout, const float* __restrict__ bout,
                   float* __restrict__ out)
{
    extern __shared__ float smem[];
    float* s_enc  = smem;                     // [63][64]
    float* s_h    = smem + ENC_DIM * BLK;     // [128][64]
    float* s_cheb = s_h + HID * BLK;          // [16][64]

    const int tid  = threadIdx.x;
    const int base = blockIdx.x * BLK;

    // ---------------- Phase 0: geometry + Chebyshev + Fourier encoding ----------------
    if (tid < BLK) {
        const int pt = base + tid;
        float3 xx = make_float3(x[pt*3+0],      x[pt*3+1],      x[pt*3+2]);
        float3 vv = make_float3(view[pt*3+0],   view[pt*3+1],   view[pt*3+2]);
        float3 nn = make_float3(normal[pt*3+0], normal[pt*3+1], normal[pt*3+2]);
        float3 ll = make_float3(light[pt*3+0],  light[pt*3+1],  light[pt*3+2]);

        // coordinate_system(normal)
        float3 n  = norm3(nn, 1e-6f);
        float sgn = (n.z >= 0.0f) ? 1.0f : -1.0f;
        float s_z = sgn + n.z;
        float safe = (fabsf(s_z) < 1e-6f) ? copysignf(1e-6f, s_z) : s_z;
        float a = -1.0f / safe;
        float b = n.x * n.y * a;
        float3 s = make_float3(n.x*n.x*a*sgn + 1.0f, b*sgn, -n.x*sgn);
        s = norm3(s, 1e-6f);
        float3 t = norm3(cross3(s, n), 1e-6f);
        s = norm3(cross3(n, t), 1e-6f);

        // to_local
        float3 v  = norm3(vv, 1e-6f);
        float3 wo = norm3(make_float3(v.x*s.x + v.y*s.y + v.z*s.z,
                                      v.x*t.x + v.y*t.y + v.z*t.z,
                                      v.x*n.x + v.y*n.y + v.z*n.z), 1e-7f);
        float3 wi = norm3(make_float3(ll.x*s.x + ll.y*s.y + ll.z*s.z,
                                      ll.x*t.x + ll.y*t.y + ll.z*t.z,
                                      ll.x*n.x + ll.y*n.y + ll.z*n.z), 1e-7f);

        // cos_D_phi(-wi, wo)
        float num = -(wi.x*wo.x + wi.y*wo.y);
        float den = sqrtf((wo.x*wo.x + wo.y*wo.y) * (wi.x*wi.x + wi.y*wi.y));
        float cp  = num / den;
        cp = fminf(1.0f, fmaxf(-1.0f, cp));

        // Chebyshev basis T0..T15
        float c0 = 1.0f, c1 = cp;
        s_cheb[0*BLK + tid] = c0;
        s_cheb[1*BLK + tid] = c1;
        #pragma unroll
        for (int o = 2; o < ORDER; o++) {
            float c2 = 2.0f*cp*c1 - c0;
            s_cheb[o*BLK + tid] = c2;
            c0 = c1; c1 = c2;
        }

        // Fourier encoding: [x, sin(x*2^f), cos(x*2^f)] feature-major in smem
        s_enc[0*BLK + tid] = xx.x;
        s_enc[1*BLK + tid] = xx.y;
        s_enc[2*BLK + tid] = xx.z;
        float fr = 1.0f;
        #pragma unroll
        for (int f = 0; f < N_FREQS; f++) {
            float sv, cv;
            sincosf(xx.x * fr, &sv, &cv);
            s_enc[(3  + f*3 + 0)*BLK + tid] = sv;
            s_enc[(33 + f*3 + 0)*BLK + tid] = cv;
            sincosf(xx.y * fr, &sv, &cv);
            s_enc[(3  + f*3 + 1)*BLK + tid] = sv;
            s_enc[(33 + f*3 + 1)*BLK + tid] = cv;
            sincosf(xx.z * fr, &sv, &cv);
            s_enc[(3  + f*3 + 2)*BLK + tid] = sv;
            s_enc[(33 + f*3 + 2)*BLK + tid] = cv;
            fr *= 2.0f;
        }
    }
    __syncthreads();

    // ---------------- Register-tiled GEMM: 8x8 per thread ----------------
    const int rg = tid >> 3;   // output row group (0..15) -> rows rg*8..rg*8+7
    const int cg = tid & 7;    // point col group  (0..7)  -> cols cg*8..cg*8+7
    float acc[8][8];

    // ---- Layer 0: s_h = leaky_relu(enc @ W0 + b0), K = 63 ----
    {
        #pragma unroll
        for (int r = 0; r < 8; r++) {
            float bb = b0[rg*8 + r];
            #pragma unroll
            for (int c = 0; c < 8; c++) acc[r][c] = bb;
        }
        #pragma unroll 3
        for (int k = 0; k < ENC_DIM; k++) {
            float4 w0v = *(const float4*)(W0 + k*HID + rg*8);
            float4 w1v = *(const float4*)(W0 + k*HID + rg*8 + 4);
            float4 a0  = *(const float4*)(s_enc + k*BLK + cg*8);
            float4 a1  = *(const float4*)(s_enc + k*BLK + cg*8 + 4);
            float wv[8] = {w0v.x,w0v.y,w0v.z,w0v.w,w1v.x,w1v.y,w1v.z,w1v.w};
            float av[8] = {a0.x,a0.y,a0.z,a0.w,a1.x,a1.y,a1.z,a1.w};
            #pragma unroll
            for (int r = 0; r < 8; r++)
                #pragma unroll
                for (int c = 0; c < 8; c++) acc[r][c] += wv[r]*av[c];
        }
        #pragma unroll
        for (int r = 0; r < 8; r++) {
            float vals[8];
            #pragma unroll
            for (int c = 0; c < 8; c++) {
                float vv = acc[r][c];
                vals[c] = vv > 0.0f ? vv : 0.01f*vv;
            }
            *(float4*)(s_h + (rg*8+r)*BLK + cg*8)     = make_float4(vals[0],vals[1],vals[2],vals[3]);
            *(float4*)(s_h + (rg*8+r)*BLK + cg*8 + 4) = make_float4(vals[4],vals[5],vals[6],vals[7]);
        }
    }
    __syncthreads();

    // ---- Hidden layers: h = leaky_relu([h, enc] @ Wh[l] + bh[l]), K = 191 ----
    for (int l = 0; l < NLAYERS; l++) {
        const float* W = Wh + (size_t)l * (KDIM*HID);
        #pragma unroll
        for (int r = 0; r < 8; r++) {
            float bb = bh[l*HID + rg*8 + r];
            #pragma unroll
            for (int c = 0; c < 8; c++) acc[r][c] = bb;
        }
        // k in [0, 128): input from s_h
        #pragma unroll 2
        for (int k = 0; k < HID; k++) {
            float4 w0v = *(const float4*)(W + k*HID + rg*8);
            float4 w1v = *(const float4*)(W + k*HID + rg*8 + 4);
            float4 a0  = *(const float4*)(s_h + k*BLK + cg*8);
            float4 a1  = *(const float4*)(s_h + k*BLK + cg*8 + 4);
            float wv[8] = {w0v.x,w0v.y,w0v.z,w0v.w,w1v.x,w1v.y,w1v.z,w1v.w};
            float av[8] = {a0.x,a0.y,a0.z,a0.w,a1.x,a1.y,a1.z,a1.w};
            #pragma unroll
            for (int r = 0; r < 8; r++)
                #pragma unroll
                for (int c = 0; c < 8; c++) acc[r][c] += wv[r]*av[c];
        }
        // k in [128, 191): input from s_enc
        #pragma unroll 3
        for (int k = 0; k < ENC_DIM; k++) {
            float4 w0v = *(const float4*)(W + (HID+k)*HID + rg*8);
            float4 w1v = *(const float4*)(W + (HID+k)*HID + rg*8 + 4);
            float4 a0  = *(const float4*)(s_enc + k*BLK + cg*8);
            float4 a1  = *(const float4*)(s_enc + k*BLK + cg*8 + 4);
            float wv[8] = {w0v.x,w0v.y,w0v.z,w0v.w,w1v.x,w1v.y,w1v.z,w1v.w};
            float av[8] = {a0.x,a0.y,a0.z,a0.w,a1.x,a1.y,a1.z,a1.w};
            #pragma unroll
            for (int r = 0; r < 8; r++)
                #pragma unroll
                for (int c = 0; c < 8; c++) acc[r][c] += wv[r]*av[c];
        }
        __syncthreads();   // all reads of s_h done before overwrite
        #pragma unroll
        for (int r = 0; r < 8; r++) {
            float vals[8];
            #pragma unroll
            for (int c = 0; c < 8; c++) {
                float vv = acc[r][c];
                vals[c] = vv > 0.0f ? vv : 0.01f*vv;
            }
            *(float4*)(s_h + (rg*8+r)*BLK + cg*8)     = make_float4(vals[0],vals[1],vals[2],vals[3]);
            *(float4*)(s_h + (rg*8+r)*BLK + cg*8 + 4) = make_float4(vals[4],vals[5],vals[6],vals[7]);
        }
        __syncthreads();
    }

    // ---- Output layer: coeffs = h @ Wout + bout (no activation), K = 128 ----
    {
        const int pt   = tid >> 1;   // 2 threads per point
        const int half = tid & 1;    // 24 output features each
        float facc[24];
        #pragma unroll
        for (int j = 0; j < 24; j++) facc[j] = bout[half*24 + j];
        #pragma unroll 2
        for (int k = 0; k < HID; k++) {
            float hv = s_h[k*BLK + pt];
            const float4* wp = (const float4*)(Wout + k*OUTD + half*24);
            #pragma unroll
            for (int q = 0; q < 6; q++) {
                float4 w = wp[q];
                facc[q*4+0] += hv*w.x;
                facc[q*4+1] += hv*w.y;
                facc[q*4+2] += hv*w.z;
                facc[q*4+3] += hv*w.w;
            }
        }
        __syncthreads();   // all reads of s_h done; reuse it for coeffs
        #pragma unroll
        for (int j = 0; j < 24; j++) s_h[(half*24 + j)*BLK + pt] = facc[j];
    }
    __syncthreads();

    // ---- Combine with Chebyshev basis: rgb[f] = sum_o coeffs[f][o] * T_o ----
    if (tid < BLK) {
        #pragma unroll
        for (int f = 0; f < 3; f++) {
            float sum = 0.0f;
            #pragma unroll
            for (int o = 0; o < ORDER; o++)
                sum += s_h[(f*ORDER + o)*BLK + tid] * s_cheb[o*BLK + tid];
            out[(base + tid)*3 + f] = sum;
        }
    }
}

extern "C" void kernel_launch(void* const* d_in, const int* in_sizes, int n_in,
                              void* d_out, int out_size)
{
    const float* x      = (const float*)d_in[0];
    const float* view   = (const float*)d_in[1];
    const float* normal = (const float*)d_in[2];
    const float* light  = (const float*)d_in[3];
    const float* W0     = (const float*)d_in[4];
    const float* b0     = (const float*)d_in[5];
    const float* Wh     = (const float*)d_in[6];
    const float* bh     = (const float*)d_in[7];
    const float* Wout   = (const float*)d_in[8];
    const float* bout   = (const float*)d_in[9];
    float* out = (float*)d_out;

    const size_t smem = (size_t)(ENC_DIM*BLK + HID*BLK + ORDER*BLK) * sizeof(float); // 52,992 B
    cudaFuncSetAttribute(fourier_mlp_kernel,
                         cudaFuncAttributeMaxDynamicSharedMemorySize, (int)smem);

    fourier_mlp_kernel<<<N_PTS / BLK, THREADS, smem>>>(
        x, view, normal, light, W0, b0, Wh, bh, Wout, bout, out);
}

// round 3
// speedup vs baseline: 2.2978x; 2.2978x over previous
#include <cuda_runtime.h>
#include <cuda_bf16.h>
#include <math.h>
#include <stdint.h>

#define TPB   128
#define NBLK  2048

// ---------------- smem layout (bytes) ----------------
#define SM_AHI  0u            // A hi: 128 pts x 384B (192 bf16: h[0..127], enc[128..190], bias[191])
#define SM_ALO  49152u        // A lo: same
#define SM_WHI  98304u        // weight hi region (49152 max)
#define SM_WLO  147456u       // weight lo region
#define SM_CHEB 196608u       // 128 x 68B (16 f32 + 4B pad, conflict-free)
#define SM_TOTAL 205312u

// ---------------- global weight scratch (pre-swizzled smem images) ----------------
#define IMG_L0  0u
#define P_L0    16384u        // 64 rows x 256B
#define P_HID   49152u        // 192 rows x 256B
#define IMG_HID(l) (32768u + (uint32_t)((l) - 1) * 98304u)   // l = 1..5
#define IMG_OUT 524288u
#define P_OUT   16384u        // 128 rows x 128B (N padded to 64)
__device__ __align__(16) unsigned char g_wscratch[557056];

// ---------------- PTX helpers (all plain sm_80+ PTX, no 'a' features) ----------------
__device__ __forceinline__ uint32_t smem_u32(const void* p) {
    uint32_t a;
    asm("{ .reg .u64 t; cvta.to.shared.u64 t, %1; cvt.u32.u64 %0, t; }" : "=r"(a) : "l"(p));
    return a;
}
__device__ __forceinline__ void ldsm_x4(uint32_t& r0, uint32_t& r1, uint32_t& r2, uint32_t& r3, uint32_t a) {
    asm volatile("ldmatrix.sync.aligned.m8n8.x4.shared.b16 {%0,%1,%2,%3}, [%4];"
        : "=r"(r0), "=r"(r1), "=r"(r2), "=r"(r3) : "r"(a));
}
__device__ __forceinline__ void ldsm_x4t(uint32_t& r0, uint32_t& r1, uint32_t& r2, uint32_t& r3, uint32_t a) {
    asm volatile("ldmatrix.sync.aligned.m8n8.x4.trans.shared.b16 {%0,%1,%2,%3}, [%4];"
        : "=r"(r0), "=r"(r1), "=r"(r2), "=r"(r3) : "r"(a));
}
__device__ __forceinline__ void mma_bf16(float* d, uint32_t a0, uint32_t a1, uint32_t a2, uint32_t a3,
                                         uint32_t b0, uint32_t b1) {
    asm volatile("mma.sync.aligned.m16n8k16.row.col.f32.bf16.bf16.f32 "
        "{%0,%1,%2,%3}, {%4,%5,%6,%7}, {%8,%9}, {%0,%1,%2,%3};"
        : "+f"(d[0]), "+f"(d[1]), "+f"(d[2]), "+f"(d[3])
        : "r"(a0), "r"(a1), "r"(a2), "r"(a3), "r"(b0), "r"(b1));
}
__device__ __forceinline__ void cp16(uint32_t sdst, const void* gsrc) {
    asm volatile("cp.async.cg.shared.global [%0], [%1], 16;" :: "r"(sdst), "l"(gsrc));
}
#define CP_COMMIT() asm volatile("cp.async.commit_group;")
template<int N> __device__ __forceinline__ void cp_wait() {
    asm volatile("cp.async.wait_group %0;" :: "n"(N));
}
__device__ __forceinline__ void copy_async(uint32_t sdst, const unsigned char* gsrc, uint32_t bytes, int tid) {
    for (uint32_t i = (uint32_t)tid * 16u; i < bytes; i += (uint32_t)TPB * 16u)
        cp16(sdst + i, gsrc + i);
}

// swizzled byte offset inside a row-image: rowB-byte rows, XOR ((row&7)<<4) within 128B group
__device__ __host__ __forceinline__ uint32_t swz_off(uint32_t row, uint32_t cb, uint32_t rowB) {
    return row * rowB + (cb & ~127u) + ((cb & 127u) ^ ((row & 7u) << 4));
}

// ---------------- weight converter: fp32 -> (hi, lo) bf16 swizzled smem images ----------------
__global__ void convert_weights_kernel(const float* __restrict__ W0, const float* __restrict__ b0,
                                       const float* __restrict__ Wh, const float* __restrict__ bh,
                                       const float* __restrict__ Wout)
{
    int idx = blockIdx.x * blockDim.x + threadIdx.x;
    if (idx >= 139264) return;
    float w; uint32_t img, part, rowB, k, n;
    if (idx < 8192) {                       // L0: K=64 (row 63 = bias), N=128
        k = (uint32_t)(idx >> 7); n = (uint32_t)(idx & 127);
        img = IMG_L0; part = P_L0; rowB = 256;
        w = (k < 63) ? W0[k * 128 + n] : b0[n];
    } else if (idx < 131072) {              // hidden: K=192 (row 191 = bias), N=128
        int t = idx - 8192; int l = t / 24576; int r = t % 24576;
        k = (uint32_t)(r >> 7); n = (uint32_t)(r & 127);
        img = IMG_HID(l + 1); part = P_HID; rowB = 256;
        w = (k < 191) ? Wh[((uint32_t)l * 191 + k) * 128 + n] : bh[l * 128 + n];
    } else {                                // out: K=128, N=48 padded to 64
        int t = idx - 131072;
        k = (uint32_t)(t >> 6); n = (uint32_t)(t & 63);
        img = IMG_OUT; part = P_OUT; rowB = 128;
        w = (n < 48) ? Wout[k * 48 + n] : 0.0f;
    }
    __nv_bfloat16 hi = __float2bfloat16(w);
    __nv_bfloat16 lo = __float2bfloat16(w - __bfloat162float(hi));
    uint32_t off = swz_off(k, n * 2, rowB);
    *(__nv_bfloat16*)(g_wscratch + img + off)        = hi;
    *(__nv_bfloat16*)(g_wscratch + img + part + off) = lo;
}

// ---------------- small math utils ----------------
__device__ __forceinline__ float3 norm3(float3 v, float eps) {
    float n = sqrtf(v.x * v.x + v.y * v.y + v.z * v.z);
    float inv = 1.0f / fmaxf(n, eps);
    return make_float3(v.x * inv, v.y * inv, v.z * inv);
}
__device__ __forceinline__ float3 cross3(float3 a, float3 b) {
    return make_float3(a.y * b.z - a.z * b.y, a.z * b.x - a.x * b.z, a.x * b.y - a.y * b.x);
}
__device__ __forceinline__ uint32_t packbf(float a, float b) {
    __nv_bfloat162 p; p.x = __float2bfloat16(a); p.y = __float2bfloat16(b);
    return *(uint32_t*)&p;
}

// ---------------- MMA pass over one weight region ----------------
// A: [128 pts][K] swizzled bf16 at SM_AHI / SM_ALO. W: [K][N] swizzled bf16 at wreg.
// Warp computes all 128 pts x NT*8 outputs starting at column n0.
template<int KSTEPS, int NT, int ROWB, bool DUAL>
__device__ __forceinline__ void mma_pass(uint32_t sb, uint32_t wreg, int kbaseA, int n0,
                                         int lane, float (&acc)[8][NT][4])
{
    const uint32_t l15 = (uint32_t)(lane & 15);
    const uint32_t lh  = (uint32_t)(lane >> 4);
    #pragma unroll
    for (int s = 0; s < KSTEPS; s++) {
        uint32_t b[NT][2];
        #pragma unroll
        for (int t = 0; t < NT / 2; t++) {
            uint32_t krow = (uint32_t)(16 * s) + l15;
            uint32_t cb = (uint32_t)(n0 * 2 + t * 32) + (lh << 4);
            uint32_t off = swz_off(krow, cb, (uint32_t)ROWB);
            ldsm_x4t(b[2 * t][0], b[2 * t][1], b[2 * t + 1][0], b[2 * t + 1][1], sb + wreg + off);
        }
        const uint32_t cbA = (uint32_t)((kbaseA + 16 * s) * 2) + (lh << 4);
        #pragma unroll
        for (int m = 0; m < 8; m++) {
            uint32_t row = (uint32_t)(16 * m) + l15;
            uint32_t off = swz_off(row, cbA, 384u);
            uint32_t a0, a1, a2, a3;
            ldsm_x4(a0, a1, a2, a3, sb + SM_AHI + off);
            #pragma unroll
            for (int n = 0; n < NT; n++) mma_bf16(acc[m][n], a0, a1, a2, a3, b[n][0], b[n][1]);
            if (DUAL) {
                ldsm_x4(a0, a1, a2, a3, sb + SM_ALO + off);
                #pragma unroll
                for (int n = 0; n < NT; n++) mma_bf16(acc[m][n], a0, a1, a2, a3, b[n][0], b[n][1]);
            }
        }
    }
}

// hidden-layer epilogue: leaky-relu, split hi/lo, store into A h-region (cols 0..127)
__device__ __forceinline__ void epilogue_store(unsigned char* smem, float (&acc)[8][4][4],
                                               int lane, int n0)
{
    const int r  = lane >> 2;
    const int c2 = (lane & 3) * 2;
    #pragma unroll
    for (int m = 0; m < 8; m++)
        #pragma unroll
        for (int n = 0; n < 4; n++) {
            const uint32_t cb = (uint32_t)((n0 + 8 * n + c2) * 2);
            #pragma unroll
            for (int h = 0; h < 2; h++) {
                uint32_t row = (uint32_t)(16 * m + r + 8 * h);
                float v0 = acc[m][n][2 * h + 0];
                float v1 = acc[m][n][2 * h + 1];
                v0 = v0 > 0.0f ? v0 : 0.01f * v0;
                v1 = v1 > 0.0f ? v1 : 0.01f * v1;
                __nv_bfloat16 h0 = __float2bfloat16(v0), h1 = __float2bfloat16(v1);
                float l0 = v0 - __bfloat162float(h0), l1 = v1 - __bfloat162float(h1);
                __nv_bfloat162 hp; hp.x = h0; hp.y = h1;
                uint32_t off = swz_off(row, cb, 384u);
                *(uint32_t*)(smem + SM_AHI + off) = *(uint32_t*)&hp;
                *(uint32_t*)(smem + SM_ALO + off) = packbf(l0, l1);
            }
        }
}

// ---------------- main kernel ----------------
extern "C" __global__ void __launch_bounds__(TPB, 1)
fourier_mma_kernel(const float* __restrict__ x, const float* __restrict__ view,
                   const float* __restrict__ normal, const float* __restrict__ light,
                   const float* __restrict__ bout, float* __restrict__ out)
{
    extern __shared__ __align__(16) unsigned char smem[];
    const uint32_t sb = smem_u32(smem);
    const int tid  = threadIdx.x;
    const int lane = tid & 31;
    const int warp = tid >> 5;

    // prefetch L0 weights (group GH0, GL0) — overlaps with geometry below
    copy_async(sb + SM_WHI, g_wscratch + IMG_L0, P_L0, tid);        CP_COMMIT();
    copy_async(sb + SM_WLO, g_wscratch + IMG_L0 + P_L0, P_L0, tid); CP_COMMIT();

    // ---- geometry + Chebyshev + Fourier encoding (thread = point) ----
    {
        const int pt = blockIdx.x * TPB + tid;
        float3 xx = make_float3(x[pt * 3 + 0], x[pt * 3 + 1], x[pt * 3 + 2]);
        float3 vv = make_float3(view[pt * 3 + 0], view[pt * 3 + 1], view[pt * 3 + 2]);
        float3 nn = make_float3(normal[pt * 3 + 0], normal[pt * 3 + 1], normal[pt * 3 + 2]);
        float3 ll = make_float3(light[pt * 3 + 0], light[pt * 3 + 1], light[pt * 3 + 2]);

        float3 n = norm3(nn, 1e-6f);
        float sgn = (n.z >= 0.0f) ? 1.0f : -1.0f;
        float s_z = sgn + n.z;
        float safe = (fabsf(s_z) < 1e-6f) ? copysignf(1e-6f, s_z) : s_z;
        float a = -1.0f / safe;
        float b = n.x * n.y * a;
        float3 s = make_float3(n.x * n.x * a * sgn + 1.0f, b * sgn, -n.x * sgn);
        s = norm3(s, 1e-6f);
        float3 t = norm3(cross3(s, n), 1e-6f);
        s = norm3(cross3(n, t), 1e-6f);

        float3 v = norm3(vv, 1e-6f);
        float3 wo = norm3(make_float3(v.x * s.x + v.y * s.y + v.z * s.z,
                                      v.x * t.x + v.y * t.y + v.z * t.z,
                                      v.x * n.x + v.y * n.y + v.z * n.z), 1e-7f);
        float3 wi = norm3(make_float3(ll.x * s.x + ll.y * s.y + ll.z * s.z,
                                      ll.x * t.x + ll.y * t.y + ll.z * t.z,
                                      ll.x * n.x + ll.y * n.y + ll.z * n.z), 1e-7f);
        float num = -(wi.x * wo.x + wi.y * wo.y);
        float den = sqrtf((wo.x * wo.x + wo.y * wo.y) * (wi.x * wi.x + wi.y * wi.y));
        float cp = fminf(1.0f, fmaxf(-1.0f, num / den));

        float c0 = 1.0f, c1 = cp;
        *(float*)(smem + SM_CHEB + tid * 68 + 0) = c0;
        *(float*)(smem + SM_CHEB + tid * 68 + 4) = c1;
        #pragma unroll
        for (int o = 2; o < 16; o++) {
            float c2v = 2.0f * cp * c1 - c0;
            *(float*)(smem + SM_CHEB + tid * 68 + o * 4) = c2v;
            c0 = c1; c1 = c2v;
        }

        float enc[64];
        enc[0] = xx.x; enc[1] = xx.y; enc[2] = xx.z;
        float fr = 1.0f;
        #pragma unroll
        for (int f = 0; f < 10; f++) {
            float sv, cv;
            sincosf(xx.x * fr, &sv, &cv); enc[3 + f * 3 + 0] = sv; enc[33 + f * 3 + 0] = cv;
            sincosf(xx.y * fr, &sv, &cv); enc[3 + f * 3 + 1] = sv; enc[33 + f * 3 + 1] = cv;
            sincosf(xx.z * fr, &sv, &cv); enc[3 + f * 3 + 2] = sv; enc[33 + f * 3 + 2] = cv;
            fr *= 2.0f;
        }
        enc[63] = 1.0f;                      // bias slot

        // enc occupies A cols 128..191: byte offsets 256..383, group = 256
        #pragma unroll
        for (int j = 0; j < 32; j++) {
            float e0 = enc[2 * j], e1 = enc[2 * j + 1];
            __nv_bfloat16 h0 = __float2bfloat16(e0), h1 = __float2bfloat16(e1);
            float l0 = e0 - __bfloat162float(h0), l1 = e1 - __bfloat162float(h1);
            __nv_bfloat162 hp; hp.x = h0; hp.y = h1;
            uint32_t off = swz_off((uint32_t)tid, 256u + 4u * (uint32_t)j, 384u);
            *(uint32_t*)(smem + SM_AHI + off) = *(uint32_t*)&hp;
            *(uint32_t*)(smem + SM_ALO + off) = packbf(l0, l1);
        }
    }
    cp_wait<1>();        // GH0 (W_hi L0) complete
    __syncthreads();

    const int n0 = 32 * warp;

    // ================= layer 0 (K=64, A cols 128..191) =================
    {
        float acc[8][4][4] = {};
        mma_pass<4, 4, 256, true>(sb, SM_WHI, 128, n0, lane, acc);
        __syncthreads();
        copy_async(sb + SM_WHI, g_wscratch + IMG_HID(1), P_HID, tid); CP_COMMIT();
        cp_wait<1>();    // GL0 complete
        __syncthreads();
        mma_pass<4, 4, 256, false>(sb, SM_WLO, 128, n0, lane, acc);
        __syncthreads();
        copy_async(sb + SM_WLO, g_wscratch + IMG_HID(1) + P_HID, P_HID, tid); CP_COMMIT();
        epilogue_store(smem, acc, lane, n0);
        cp_wait<1>();    // W_hi(1) complete
        __syncthreads();
    }

    // ================= hidden layers 1..5 (K=192) =================
    #pragma unroll 1
    for (int l = 1; l <= 5; l++) {
        const unsigned char* nimg = g_wscratch + ((l == 5) ? IMG_OUT : IMG_HID(l + 1));
        const uint32_t npart = (l == 5) ? P_OUT : P_HID;
        float acc[8][4][4] = {};
        mma_pass<12, 4, 256, true>(sb, SM_WHI, 0, n0, lane, acc);
        __syncthreads();
        copy_async(sb + SM_WHI, nimg, npart, tid); CP_COMMIT();
        cp_wait<1>();
        __syncthreads();
        mma_pass<12, 4, 256, false>(sb, SM_WLO, 0, n0, lane, acc);
        __syncthreads();
        copy_async(sb + SM_WLO, nimg + npart, npart, tid); CP_COMMIT();
        epilogue_store(smem, acc, lane, n0);
        cp_wait<1>();
        __syncthreads();
    }

    // ================= output layer (K=128, N=64 padded, warp n-chunk 16) =================
    {
        const int nf0 = 16 * warp;
        float acc[8][2][4] = {};
        mma_pass<8, 2, 128, true>(sb, SM_WHI, 0, nf0, lane, acc);
        __syncthreads();
        cp_wait<0>();    // W_lo(out) complete
        __syncthreads();
        mma_pass<8, 2, 128, false>(sb, SM_WLO, 0, nf0, lane, acc);
        __syncthreads();

        // stage coeffs into (now free) W_HI region: [pt][65 f32] (stride 65 avoids conflicts)
        const int r  = lane >> 2;
        const int c2 = (lane & 3) * 2;
        #pragma unroll
        for (int m = 0; m < 8; m++)
            #pragma unroll
            for (int n = 0; n < 2; n++) {
                int col = nf0 + 8 * n + c2;
                #pragma unroll
                for (int h = 0; h < 2; h++) {
                    int row = 16 * m + r + 8 * h;
                    float* dst = (float*)(smem + SM_WHI) + row * 65 + col;
                    dst[0] = acc[m][n][2 * h + 0];
                    dst[1] = acc[m][n][2 * h + 1];
                }
            }
        __syncthreads();

        // contraction with Chebyshev basis
        float ch[16];
        #pragma unroll
        for (int o = 0; o < 16; o++) ch[o] = *(float*)(smem + SM_CHEB + tid * 68 + o * 4);
        const float* cf = (float*)(smem + SM_WHI) + tid * 65;
        const int pt = blockIdx.x * TPB + tid;
        #pragma unroll
        for (int f = 0; f < 3; f++) {
            float sum = 0.0f;
            #pragma unroll
            for (int o = 0; o < 16; o++)
                sum += (cf[f * 16 + o] + __ldg(bout + f * 16 + o)) * ch[o];
            out[pt * 3 + f] = sum;
        }
    }
}

// ---------------- launch ----------------
extern "C" void kernel_launch(void* const* d_in, const int* in_sizes, int n_in,
                              void* d_out, int out_size)
{
    const float* x      = (const float*)d_in[0];
    const float* view   = (const float*)d_in[1];
    const float* normal = (const float*)d_in[2];
    const float* light  = (const float*)d_in[3];
    const float* W0     = (const float*)d_in[4];
    const float* b0     = (const float*)d_in[5];
    const float* Wh     = (const float*)d_in[6];
    const float* bh     = (const float*)d_in[7];
    const float* Wout   = (const float*)d_in[8];
    const float* bout   = (const float*)d_in[9];
    float* out = (float*)d_out;

    convert_weights_kernel<<<544, 256>>>(W0, b0, Wh, bh, Wout);

    cudaFuncSetAttribute(fourier_mma_kernel,
                         cudaFuncAttributeMaxDynamicSharedMemorySize, (int)SM_TOTAL);
    fourier_mma_kernel<<<NBLK, TPB, SM_TOTAL>>>(x, view, normal, light, bout, out);
}

// round 6
// speedup vs baseline: 2.7256x; 1.1862x over previous
#include <cuda_runtime.h>
#include <cuda_bf16.h>
#include <math.h>
#include <stdint.h>

#define TPB   256
#define PTS   128
#define NBLK  2048

// ---------------- smem layout (bytes) ----------------
#define SM_AHI  0u            // A hi: 128 pts x 384B (192 bf16: h[0..127], enc[128..190], bias[191])
#define SM_ALO  49152u        // A lo: same
#define SM_WHI  98304u        // weight hi region (49152 max)
#define SM_WLO  147456u       // weight lo region
#define SM_CHEB 196608u       // 128 x 68B
#define SM_TOTAL 205312u

// ---------------- global weight scratch (pre-swizzled smem images) ----------------
#define IMG_L0  0u
#define P_L0    16384u        // 64 rows x 256B
#define P_HID   49152u        // 192 rows x 256B
#define IMG_HID(l) (32768u + (uint32_t)((l) - 1) * 98304u)   // l = 1..5
#define IMG_OUT 524288u
#define P_OUT   16384u        // 128 rows x 128B (N padded to 64)
__device__ __align__(16) unsigned char g_wscratch[557056];

// ---------------- PTX helpers ----------------
__device__ __forceinline__ uint32_t smem_u32(const void* p) {
    uint32_t a;
    asm("{ .reg .u64 t; cvta.to.shared.u64 t, %1; cvt.u32.u64 %0, t; }" : "=r"(a) : "l"(p));
    return a;
}
__device__ __forceinline__ void ldsm_x4(uint32_t& r0, uint32_t& r1, uint32_t& r2, uint32_t& r3, uint32_t a) {
    asm volatile("ldmatrix.sync.aligned.m8n8.x4.shared.b16 {%0,%1,%2,%3}, [%4];"
        : "=r"(r0), "=r"(r1), "=r"(r2), "=r"(r3) : "r"(a));
}
__device__ __forceinline__ void ldsm_x4t(uint32_t& r0, uint32_t& r1, uint32_t& r2, uint32_t& r3, uint32_t a) {
    asm volatile("ldmatrix.sync.aligned.m8n8.x4.trans.shared.b16 {%0,%1,%2,%3}, [%4];"
        : "=r"(r0), "=r"(r1), "=r"(r2), "=r"(r3) : "r"(a));
}
__device__ __forceinline__ void mma_bf16(float* d, uint32_t a0, uint32_t a1, uint32_t a2, uint32_t a3,
                                         uint32_t b0, uint32_t b1) {
    asm volatile("mma.sync.aligned.m16n8k16.row.col.f32.bf16.bf16.f32 "
        "{%0,%1,%2,%3}, {%4,%5,%6,%7}, {%8,%9}, {%0,%1,%2,%3};"
        : "+f"(d[0]), "+f"(d[1]), "+f"(d[2]), "+f"(d[3])
        : "r"(a0), "r"(a1), "r"(a2), "r"(a3), "r"(b0), "r"(b1));
}
__device__ __forceinline__ void cp16(uint32_t sdst, const void* gsrc) {
    asm volatile("cp.async.cg.shared.global [%0], [%1], 16;" :: "r"(sdst), "l"(gsrc));
}
#define CP_COMMIT() asm volatile("cp.async.commit_group;")
template<int N> __device__ __forceinline__ void cp_wait() {
    asm volatile("cp.async.wait_group %0;" :: "n"(N));
}
__device__ __forceinline__ void copy_async(uint32_t sdst, const unsigned char* gsrc, uint32_t bytes, int tid) {
    for (uint32_t i = (uint32_t)tid * 16u; i < bytes; i += (uint32_t)TPB * 16u)
        cp16(sdst + i, gsrc + i);
}
__device__ __host__ __forceinline__ uint32_t swz_off(uint32_t row, uint32_t cb, uint32_t rowB) {
    return row * rowB + (cb & ~127u) + ((cb & 127u) ^ ((row & 7u) << 4));
}

// ---------------- weight converter ----------------
__global__ void convert_weights_kernel(const float* __restrict__ W0, const float* __restrict__ b0,
                                       const float* __restrict__ Wh, const float* __restrict__ bh,
                                       const float* __restrict__ Wout)
{
    int idx = blockIdx.x * blockDim.x + threadIdx.x;
    if (idx >= 139264) return;
    float w; uint32_t img, part, rowB, k, n;
    if (idx < 8192) {                       // L0: K=64 (row 63 = bias), N=128
        k = (uint32_t)(idx >> 7); n = (uint32_t)(idx & 127);
        img = IMG_L0; part = P_L0; rowB = 256;
        w = (k < 63) ? W0[k * 128 + n] : b0[n];
    } else if (idx < 131072) {              // hidden: K=192 (row 191 = bias), N=128
        int t = idx - 8192; int l = t / 24576; int r = t % 24576;
        k = (uint32_t)(r >> 7); n = (uint32_t)(r & 127);
        img = IMG_HID(l + 1); part = P_HID; rowB = 256;
        w = (k < 191) ? Wh[((uint32_t)l * 191 + k) * 128 + n] : bh[l * 128 + n];
    } else {                                // out: K=128, N=48 padded to 64
        int t = idx - 131072;
        k = (uint32_t)(t >> 6); n = (uint32_t)(t & 63);
        img = IMG_OUT; part = P_OUT; rowB = 128;
        w = (n < 48) ? Wout[k * 48 + n] : 0.0f;
    }
    __nv_bfloat16 hi = __float2bfloat16(w);
    __nv_bfloat16 lo = __float2bfloat16(w - __bfloat162float(hi));
    uint32_t off = swz_off(k, n * 2, rowB);
    *(__nv_bfloat16*)(g_wscratch + img + off)        = hi;
    *(__nv_bfloat16*)(g_wscratch + img + part + off) = lo;
}

// ---------------- small math utils ----------------
__device__ __forceinline__ float3 norm3(float3 v, float eps) {
    float n = sqrtf(v.x * v.x + v.y * v.y + v.z * v.z);
    float inv = 1.0f / fmaxf(n, eps);
    return make_float3(v.x * inv, v.y * inv, v.z * inv);
}
__device__ __forceinline__ float3 cross3(float3 a, float3 b) {
    return make_float3(a.y * b.z - a.z * b.y, a.z * b.x - a.x * b.z, a.x * b.y - a.y * b.x);
}
__device__ __forceinline__ uint32_t packbf(float a, float b) {
    __nv_bfloat162 p; p.x = __float2bfloat16(a); p.y = __float2bfloat16(b);
    return *(uint32_t*)&p;
}

// ---------------- MMA pass over one weight region ----------------
// Warp computes rows [m0, m0+16*MT) x cols [n0, n0+8*NT) of the layer output.
template<int KSTEPS, int MT, int NT, int ROWB, bool DUAL>
__device__ __forceinline__ void mma_pass(uint32_t sb, uint32_t wreg, int kbaseA,
                                         int m0, int n0, int lane, float (&acc)[MT][NT][4])
{
    const uint32_t l15 = (uint32_t)(lane & 15);
    const uint32_t lh  = (uint32_t)(lane >> 4);
    #pragma unroll
    for (int s = 0; s < KSTEPS; s++) {
        uint32_t b[NT][2];
        #pragma unroll
        for (int t = 0; t < NT / 2; t++) {
            uint32_t krow = (uint32_t)(16 * s) + l15;
            uint32_t cb = (uint32_t)(n0 * 2 + t * 32) + (lh << 4);
            uint32_t off = swz_off(krow, cb, (uint32_t)ROWB);
            ldsm_x4t(b[2 * t][0], b[2 * t][1], b[2 * t + 1][0], b[2 * t + 1][1], sb + wreg + off);
        }
        const uint32_t cbA = (uint32_t)((kbaseA + 16 * s) * 2) + (lh << 4);
        #pragma unroll
        for (int m = 0; m < MT; m++) {
            uint32_t row = (uint32_t)(m0 + 16 * m) + l15;
            uint32_t off = swz_off(row, cbA, 384u);
            uint32_t a0, a1, a2, a3;
            ldsm_x4(a0, a1, a2, a3, sb + SM_AHI + off);
            #pragma unroll
            for (int n = 0; n < NT; n++) mma_bf16(acc[m][n], a0, a1, a2, a3, b[n][0], b[n][1]);
            if (DUAL) {
                ldsm_x4(a0, a1, a2, a3, sb + SM_ALO + off);
                #pragma unroll
                for (int n = 0; n < NT; n++) mma_bf16(acc[m][n], a0, a1, a2, a3, b[n][0], b[n][1]);
            }
        }
    }
}

// hidden-layer epilogue: leaky-relu, split hi/lo, store into A h-region
__device__ __forceinline__ void epilogue_store(unsigned char* smem, float (&acc)[2][8][4],
                                               int lane, int m0, int n0)
{
    const int r  = lane >> 2;
    const int c2 = (lane & 3) * 2;
    #pragma unroll
    for (int m = 0; m < 2; m++)
        #pragma unroll
        for (int n = 0; n < 8; n++) {
            const uint32_t cb = (uint32_t)((n0 + 8 * n + c2) * 2);
            #pragma unroll
            for (int h = 0; h < 2; h++) {
                uint32_t row = (uint32_t)(m0 + 16 * m + r + 8 * h);
                float v0 = acc[m][n][2 * h + 0];
                float v1 = acc[m][n][2 * h + 1];
                v0 = v0 > 0.0f ? v0 : 0.01f * v0;
                v1 = v1 > 0.0f ? v1 : 0.01f * v1;
                __nv_bfloat16 h0 = __float2bfloat16(v0), h1 = __float2bfloat16(v1);
                float l0 = v0 - __bfloat162float(h0), l1 = v1 - __bfloat162float(h1);
                __nv_bfloat162 hp; hp.x = h0; hp.y = h1;
                uint32_t off = swz_off(row, cb, 384u);
                *(uint32_t*)(smem + SM_AHI + off) = *(uint32_t*)&hp;
                *(uint32_t*)(smem + SM_ALO + off) = packbf(l0, l1);
            }
        }
}

// ---------------- main kernel ----------------
extern "C" __global__ void __launch_bounds__(TPB, 1)
fourier_mma_kernel(const float* __restrict__ x, const float* __restrict__ view,
                   const float* __restrict__ normal, const float* __restrict__ light,
                   const float* __restrict__ bout, float* __restrict__ out)
{
    extern __shared__ __align__(16) unsigned char smem[];
    const uint32_t sb = smem_u32(smem);
    const int tid  = threadIdx.x;
    const int lane = tid & 31;
    const int warp = tid >> 5;

    // prefetch L0 weights (overlaps geometry)
    copy_async(sb + SM_WHI, g_wscratch + IMG_L0, P_L0, tid);        CP_COMMIT();
    copy_async(sb + SM_WLO, g_wscratch + IMG_L0 + P_L0, P_L0, tid); CP_COMMIT();

    // ---- geometry + Chebyshev + Fourier encoding (threads 0..127, thread = point) ----
    if (tid < PTS) {
        const int pt = blockIdx.x * PTS + tid;
        float3 xx = make_float3(x[pt * 3 + 0], x[pt * 3 + 1], x[pt * 3 + 2]);
        float3 vv = make_float3(view[pt * 3 + 0], view[pt * 3 + 1], view[pt * 3 + 2]);
        float3 nn = make_float3(normal[pt * 3 + 0], normal[pt * 3 + 1], normal[pt * 3 + 2]);
        float3 ll = make_float3(light[pt * 3 + 0], light[pt * 3 + 1], light[pt * 3 + 2]);

        float3 n = norm3(nn, 1e-6f);
        float sgn = (n.z >= 0.0f) ? 1.0f : -1.0f;
        float s_z = sgn + n.z;
        float safe = (fabsf(s_z) < 1e-6f) ? copysignf(1e-6f, s_z) : s_z;
        float a = -1.0f / safe;
        float b = n.x * n.y * a;
        float3 s = make_float3(n.x * n.x * a * sgn + 1.0f, b * sgn, -n.x * sgn);
        s = norm3(s, 1e-6f);
        float3 t = norm3(cross3(s, n), 1e-6f);
        s = norm3(cross3(n, t), 1e-6f);

        float3 v = norm3(vv, 1e-6f);
        float3 wo = norm3(make_float3(v.x * s.x + v.y * s.y + v.z * s.z,
                                      v.x * t.x + v.y * t.y + v.z * t.z,
                                      v.x * n.x + v.y * n.y + v.z * n.z), 1e-7f);
        float3 wi = norm3(make_float3(ll.x * s.x + ll.y * s.y + ll.z * s.z,
                                      ll.x * t.x + ll.y * t.y + ll.z * t.z,
                                      ll.x * n.x + ll.y * n.y + ll.z * n.z), 1e-7f);
        float num = -(wi.x * wo.x + wi.y * wo.y);
        float den = sqrtf((wo.x * wo.x + wo.y * wo.y) * (wi.x * wi.x + wi.y * wi.y));
        float cp = fminf(1.0f, fmaxf(-1.0f, num / den));

        float c0 = 1.0f, c1 = cp;
        *(float*)(smem + SM_CHEB + tid * 68 + 0) = c0;
        *(float*)(smem + SM_CHEB + tid * 68 + 4) = c1;
        #pragma unroll
        for (int o = 2; o < 16; o++) {
            float c2v = 2.0f * cp * c1 - c0;
            *(float*)(smem + SM_CHEB + tid * 68 + o * 4) = c2v;
            c0 = c1; c1 = c2v;
        }

        float enc[64];
        enc[0] = xx.x; enc[1] = xx.y; enc[2] = xx.z;
        float fr = 1.0f;
        #pragma unroll
        for (int f = 0; f < 10; f++) {
            float sv, cv;
            sincosf(xx.x * fr, &sv, &cv); enc[3 + f * 3 + 0] = sv; enc[33 + f * 3 + 0] = cv;
            sincosf(xx.y * fr, &sv, &cv); enc[3 + f * 3 + 1] = sv; enc[33 + f * 3 + 1] = cv;
            sincosf(xx.z * fr, &sv, &cv); enc[3 + f * 3 + 2] = sv; enc[33 + f * 3 + 2] = cv;
            fr *= 2.0f;
        }
        enc[63] = 1.0f;                      // bias slot

        #pragma unroll
        for (int j = 0; j < 32; j++) {
            float e0 = enc[2 * j], e1 = enc[2 * j + 1];
            __nv_bfloat16 h0 = __float2bfloat16(e0), h1 = __float2bfloat16(e1);
            float l0 = e0 - __bfloat162float(h0), l1 = e1 - __bfloat162float(h1);
            __nv_bfloat162 hp; hp.x = h0; hp.y = h1;
            uint32_t off = swz_off((uint32_t)tid, 256u + 4u * (uint32_t)j, 384u);
            *(uint32_t*)(smem + SM_AHI + off) = *(uint32_t*)&hp;
            *(uint32_t*)(smem + SM_ALO + off) = packbf(l0, l1);
        }
    }
    cp_wait<1>();        // W_hi(L0) complete
    __syncthreads();

    // warp tiling: 4 m-groups x 2 n-groups
    const int mg = warp >> 1;        // 0..3
    const int ng = warp & 1;         // 0..1
    const int m0 = mg * 32;
    const int n0h = ng * 64;         // hidden layers: 64 cols per warp

    // ================= layer 0 (K=64, A cols 128..191) =================
    {
        float acc[2][8][4] = {};
        mma_pass<4, 2, 8, 256, true>(sb, SM_WHI, 128, m0, n0h, lane, acc);
        __syncthreads();
        copy_async(sb + SM_WHI, g_wscratch + IMG_HID(1), P_HID, tid); CP_COMMIT();
        cp_wait<1>();    // W_lo(L0) complete
        __syncthreads();
        mma_pass<4, 2, 8, 256, false>(sb, SM_WLO, 128, m0, n0h, lane, acc);
        __syncthreads();
        copy_async(sb + SM_WLO, g_wscratch + IMG_HID(1) + P_HID, P_HID, tid); CP_COMMIT();
        epilogue_store(smem, acc, lane, m0, n0h);
        cp_wait<1>();    // W_hi(1) complete
        __syncthreads();
    }

    // ================= hidden layers 1..5 (K=192) =================
    #pragma unroll 1
    for (int l = 1; l <= 5; l++) {
        const unsigned char* nimg = g_wscratch + ((l == 5) ? IMG_OUT : IMG_HID(l + 1));
        const uint32_t npart = (l == 5) ? P_OUT : P_HID;
        float acc[2][8][4] = {};
        mma_pass<12, 2, 8, 256, true>(sb, SM_WHI, 0, m0, n0h, lane, acc);
        __syncthreads();
        copy_async(sb + SM_WHI, nimg, npart, tid); CP_COMMIT();
        cp_wait<1>();
        __syncthreads();
        mma_pass<12, 2, 8, 256, false>(sb, SM_WLO, 0, m0, n0h, lane, acc);
        __syncthreads();
        copy_async(sb + SM_WLO, nimg + npart, npart, tid); CP_COMMIT();
        epilogue_store(smem, acc, lane, m0, n0h);
        cp_wait<1>();
        __syncthreads();
    }

    // ================= output layer (K=128, N=64 padded) =================
    {
        const int n0o = ng * 32;     // 32 cols per warp
        float acc[2][4][4] = {};
        mma_pass<8, 2, 4, 128, true>(sb, SM_WHI, 0, m0, n0o, lane, acc);
        __syncthreads();
        cp_wait<0>();    // W_lo(out) complete
        __syncthreads();
        mma_pass<8, 2, 4, 128, false>(sb, SM_WLO, 0, m0, n0o, lane, acc);
        __syncthreads();

        // stage coeffs into (now free) W_HI region: [pt][65 f32]
        const int r  = lane >> 2;
        const int c2 = (lane & 3) * 2;
        #pragma unroll
        for (int m = 0; m < 2; m++)
            #pragma unroll
            for (int n = 0; n < 4; n++) {
                int col = n0o + 8 * n + c2;
                #pragma unroll
                for (int h = 0; h < 2; h++) {
                    int row = m0 + 16 * m + r + 8 * h;
                    float* dst = (float*)(smem + SM_WHI) + row * 65 + col;
                    dst[0] = acc[m][n][2 * h + 0];
                    dst[1] = acc[m][n][2 * h + 1];
                }
            }
        __syncthreads();

        // contraction with Chebyshev basis (threads 0..127, thread = point)
        if (tid < PTS) {
            float ch[16];
            #pragma unroll
            for (int o = 0; o < 16; o++) ch[o] = *(float*)(smem + SM_CHEB + tid * 68 + o * 4);
            const float* cf = (float*)(smem + SM_WHI) + tid * 65;
            const int pt = blockIdx.x * PTS + tid;
            #pragma unroll
            for (int f = 0; f < 3; f++) {
                float sum = 0.0f;
                #pragma unroll
                for (int o = 0; o < 16; o++)
                    sum += (cf[f * 16 + o] + __ldg(bout + f * 16 + o)) * ch[o];
                out[pt * 3 + f] = sum;
            }
        }
    }
}

// ---------------- launch ----------------
extern "C" void kernel_launch(void* const* d_in, const int* in_sizes, int n_in,
                              void* d_out, int out_size)
{
    const float* x      = (const float*)d_in[0];
    const float* view   = (const float*)d_in[1];
    const float* normal = (const float*)d_in[2];
    const float* light  = (const float*)d_in[3];
    const float* W0     = (const float*)d_in[4];
    const float* b0     = (const float*)d_in[5];
    const float* Wh     = (const float*)d_in[6];
    const float* bh     = (const float*)d_in[7];
    const float* Wout   = (const float*)d_in[8];
    const float* bout   = (const float*)d_in[9];
    float* out = (float*)d_out;

    convert_weights_kernel<<<544, 256>>>(W0, b0, Wh, bh, Wout);

    cudaFuncSetAttribute(fourier_mma_kernel,
                         cudaFuncAttributeMaxDynamicSharedMemorySize, (int)SM_TOTAL);
    fourier_mma_kernel<<<NBLK, TPB, SM_TOTAL>>>(x, view, normal, light, bout, out);
}